// round 12
// baseline (speedup 1.0000x reference)
#include <cuda_runtime.h>
#include <cuda_bf16.h>
#include <cstdint>

// BahdanauAttention with size-1 attention axis:
//   softmax over length-1 axis == 1.0 -> attention_weights = ones(B,1,1)
//   context = features (bit-exact copy). Score GEMMs are dead code.
//
// Round-11 finding: the copy-engine DtoD memcpy runs the 128 MiB copy in
// ~33.5us (vs 36.4us best SM kernel) but the serialized ones-fill kernel
// ate the gain. This round forks the fill onto a parallel graph branch
// (event fork/join onto cudaStreamPerThread) so it hides entirely under
// the memcpy. Events: lazy-created on the first (uncaptured) call,
// DisableTiming, no device memory involved; captured work is identical
// every call.

static constexpr long long Bsz = 16384;
static constexpr long long Dsz = 2048;
static constexpr long long CTX_ELEMS = Bsz * Dsz;          // 33,554,432 floats
static constexpr long long CTX_BYTES = CTX_ELEMS * 4;      // 128 MiB
static constexpr int AW_VECS = (int)(Bsz / 4);             // 4,096 float4

__global__ void __launch_bounds__(256)
ones_fill_kernel(float4* __restrict__ out_aw) {
    int tid = blockIdx.x * 256 + threadIdx.x;
    if (tid < AW_VECS) {
        out_aw[tid] = make_float4(1.f, 1.f, 1.f, 1.f);
    }
}

extern "C" void kernel_launch(void* const* d_in, const int* in_sizes, int n_in,
                              void* d_out, int out_size) {
    const float* features = (const float*)d_in[0];
    float* out = (float*)d_out;
    float4* out_aw = (float4*)(out + CTX_ELEMS);

    // Lazy one-time event creation (host-side resource only; happens on the
    // first, non-captured correctness call; device work is identical every call).
    static cudaEvent_t ev_fork = nullptr;
    static cudaEvent_t ev_join = nullptr;
    if (ev_fork == nullptr) {
        cudaEventCreateWithFlags(&ev_fork, cudaEventDisableTiming);
        cudaEventCreateWithFlags(&ev_join, cudaEventDisableTiming);
    }

    // Fork: ones-fill runs on a parallel branch, hidden under the memcpy.
    cudaEventRecord(ev_fork, 0);
    cudaStreamWaitEvent(cudaStreamPerThread, ev_fork, 0);
    ones_fill_kernel<<<(AW_VECS + 255) / 256, 256, 0, cudaStreamPerThread>>>(out_aw);
    cudaEventRecord(ev_join, cudaStreamPerThread);

    // Bulk context copy on the copy engine (main stream).
    cudaMemcpyAsync(out, features, (size_t)CTX_BYTES, cudaMemcpyDeviceToDevice, 0);

    // Join.
    cudaStreamWaitEvent((cudaStream_t)0, ev_join, 0);
}